// round 9
// baseline (speedup 1.0000x reference)
#include <cuda_runtime.h>
#include <cuda_bf16.h>
#include <stdint.h>

#define NN 2048
#define DD 1024
#define PP 6
#define BMU 64                   // unit rows (A side)
#define BN 128                   // unit cols (B side)
#define BK 32
#define NT 16                    // NN / 128
#define NBLK (NT * (NT + 1) / 2) // 136 triangular tiles
#define KST (DD / BK)            // 32 k-stages per part
#define NSTG 4                   // cp.async pipeline depth
#define ATILEB (BMU * BK * 2)    // 4096 bytes per A stage tile
#define BTILEB (BN * BK * 2)     // 8192 bytes per B stage tile
#define DYNB (NSTG * (ATILEB + BTILEB) + 1024)
#define MAXU (NBLK * PP * 2)     // 1632 max units

// -------- scratch (static device globals: allocation-free) --------
__device__ __nv_bfloat16 g_X[(size_t)PP * NN * DD]; // packed+sorted [p][n][d] bf16
__device__ float g_sqn[PP * NN];                    // [p][n] squared norms (sorted)
__device__ int g_perm[NN];                          // original row -> sorted row
__device__ int g_mask[NN];                          // sorted-space visibility mask
__device__ int g_tgt[NN];                           // sorted-space targets
__device__ unsigned g_bmask[NT];                    // per 128-block OR mask
__device__ int g_units[MAXU];                       // unit list: tile | part<<8 | half<<12
__device__ int g_nunits;
__device__ int g_ticket;
__device__ float g_pd[(size_t)NBLK * PP * 16384];   // per (tile,part) masked pdist planes
__device__ int g_ap[NN];                            // float bits, atomicMax (vals >= 0)
__device__ int g_an[NN];                            // float bits, atomicMin

// -------- PTX helpers --------
__device__ __forceinline__ void cp_async16(uint32_t dst, const void* src) {
    asm volatile("cp.async.cg.shared.global [%0], [%1], 16;\n" :: "r"(dst), "l"(src));
}
__device__ __forceinline__ void cp_commit() { asm volatile("cp.async.commit_group;\n"); }
template<int W> __device__ __forceinline__ void cp_wait() {
    asm volatile("cp.async.wait_group %0;\n" :: "n"(W));
}
__device__ __forceinline__ void ldsm_x4(uint32_t r[4], uint32_t addr) {
    asm volatile("ldmatrix.sync.aligned.m8n8.x4.shared.b16 {%0,%1,%2,%3}, [%4];\n"
                 : "=r"(r[0]), "=r"(r[1]), "=r"(r[2]), "=r"(r[3]) : "r"(addr));
}
__device__ __forceinline__ void mma_bf16(float c[4], const uint32_t a[4], uint32_t b0, uint32_t b1) {
    asm volatile("mma.sync.aligned.m16n8k16.row.col.f32.bf16.bf16.f32 "
                 "{%0,%1,%2,%3}, {%4,%5,%6,%7}, {%8,%9}, {%0,%1,%2,%3};\n"
                 : "+f"(c[0]), "+f"(c[1]), "+f"(c[2]), "+f"(c[3])
                 : "r"(a[0]), "r"(a[1]), "r"(a[2]), "r"(a[3]), "r"(b0), "r"(b1));
}
__device__ __forceinline__ float fsqrt_approx(float x) {
    float y; asm("sqrt.approx.f32 %0, %1;" : "=f"(y) : "f"(x)); return y;
}
// Swizzled byte offset inside a [rows x 32 bf16] stage tile (conflict-free).
__device__ __forceinline__ uint32_t tile_off(int r, int kc) {
    return (uint32_t)(((r >> 1) * 128) + ((((kc) + ((r & 1) << 2)) ^ ((r >> 1) & 7)) << 4));
}
__device__ __forceinline__ void tile_decode(int b, int& bi, int& bj) {
    bi = 0;
    while (b >= NT - bi) { b -= NT - bi; ++bi; }
    bj = bi + b;
}

// -------- setup: counting-sort perm (stable), masks, block masks, unit list --------
__global__ void setup_kernel(const int* __restrict__ pl, const int* __restrict__ targets) {
    __shared__ uint8_t skey[NN];
    __shared__ uint16_t srank[NN];
    __shared__ int soff[9];
    __shared__ unsigned sbm[NT];
    __shared__ int scnt[NBLK];
    int tid = threadIdx.x;
    for (int i = tid; i < NN; i += 1024)
        skey[i] = (uint8_t)(pl[2 * i] * 3 + (pl[2 * i + 1] - 3)); // key in 0..8
    __syncthreads();
    int w = tid >> 5, lane = tid & 31;
    if (w < 9) { // warp w ranks key w stably
        int base = 0;
        for (int c = 0; c < NN / 32; c++) {
            int i = c * 32 + lane;
            unsigned m = __ballot_sync(~0u, skey[i] == w);
            if (skey[i] == w) srank[i] = (uint16_t)(base + __popc(m & ((1u << lane) - 1u)));
            base += __popc(m);
        }
        if (lane == 0) soff[w] = base;
    }
    __syncthreads();
    if (tid == 0) {
        int acc = 0;
        for (int k = 0; k < 9; k++) { int c = soff[k]; soff[k] = acc; acc += c; }
    }
    __syncthreads();
    for (int i = tid; i < NN; i += 1024) {
        int pos = soff[skey[i]] + srank[i];
        g_perm[i] = pos;
        int st = pl[2 * i], en = pl[2 * i + 1];
        g_mask[pos] = (int)(((1u << (en + 1)) - 1u) & ~((1u << st) - 1u));
        g_tgt[pos] = targets[i];
    }
    __syncthreads();
    if (tid < NT) {
        unsigned u = 0;
        for (int r = 0; r < 128; r++) u |= (unsigned)g_mask[tid * 128 + r];
        sbm[tid] = u; g_bmask[tid] = u;
    }
    __syncthreads();
    if (tid < NBLK) {
        int bi, bj; tile_decode(tid, bi, bj);
        scnt[tid] = 2 * __popc(sbm[bi] & sbm[bj]);
    }
    __syncthreads();
    if (tid == 0) {
        int acc = 0;
        for (int t = 0; t < NBLK; t++) { int c = scnt[t]; scnt[t] = acc; acc += c; }
        g_nunits = acc;
        g_ticket = 0;
    }
    __syncthreads();
    if (tid < NBLK) {
        int bi, bj; tile_decode(tid, bi, bj);
        unsigned need = sbm[bi] & sbm[bj];
        int o = scnt[tid];
        for (int p = 0; p < PP; p++) if ((need >> p) & 1) {
            g_units[o++] = tid | (p << 8);
            g_units[o++] = tid | (p << 8) | (1 << 12);
        }
    }
}

// -------- pack: fp32 [n][d][P] -> bf16 [p][perm(n)][d]; sqn; init ap/an --------
__global__ void pack_kernel(const float* __restrict__ in) {
    int i = blockIdx.x;
    int tid = threadIdx.x;
    int P = g_perm[i];
    float acc[PP];
#pragma unroll
    for (int p = 0; p < PP; p++) acc[p] = 0.f;
    const float* row = in + (size_t)i * DD * PP;
    for (int dd = tid; dd < DD; dd += 256) {
#pragma unroll
        for (int p = 0; p < PP; p++) {
            float v = row[dd * PP + p];
            __nv_bfloat16 b = __float2bfloat16(v);
            float vb = __bfloat162float(b);
            g_X[((size_t)p * NN + P) * DD + dd] = b;
            acc[p] = fmaf(vb, vb, acc[p]);
        }
    }
    __shared__ float s[8][PP];
    int warp = tid >> 5, lane = tid & 31;
#pragma unroll
    for (int p = 0; p < PP; p++) {
        float v = acc[p];
#pragma unroll
        for (int o = 16; o > 0; o >>= 1) v += __shfl_xor_sync(~0u, v, o);
        if (lane == 0) s[warp][p] = v;
    }
    __syncthreads();
    if (tid < PP) {
        float v = 0.f;
#pragma unroll
        for (int w = 0; w < 8; w++) v += s[w][tid];
        g_sqn[tid * NN + P] = v;
    }
    if (tid == 0) { g_ap[i] = 0; g_an[i] = 0x7f800000; }
}

// -------- unit kernel: persistent CTAs, ticket queue over (tile,part,half) --------
extern __shared__ __align__(16) char dynsmem[];

__global__ void __launch_bounds__(256, 1) unit_kernel() {
    __shared__ float s_sqA[BMU], s_sqB[BN], s_fA[BMU], s_fB[BN];
    __shared__ int s_unit;

    int tid = threadIdx.x;
    int lane = tid & 31, warp = tid >> 5;
    int wm = warp & 3, wn = warp >> 2; // 4 row-groups x 2 col-halves; warp tile 16x64

    uint32_t dynbase = (uint32_t)__cvta_generic_to_shared(dynsmem);
    dynbase = (dynbase + 1023u) & ~1023u;
    uint32_t aB = dynbase, bB = dynbase + NSTG * ATILEB;

    int rrow = ((lane >> 3) & 1) * 8 + (lane & 7);
    int chalf = lane >> 4;

    while (true) {
        __syncthreads(); // protect smem + stage buffers reuse across units
        if (tid == 0) {
            int t = atomicAdd(&g_ticket, 1);
            s_unit = (t < g_nunits) ? g_units[t] : -1;
        }
        __syncthreads();
        int u = s_unit;
        if (u < 0) break;
        int tile = u & 255, p = (u >> 8) & 15, half = (u >> 12) & 1;
        int bi, bj; tile_decode(tile, bi, bj);
        int i0 = bi * 128 + half * BMU, j0 = bj * 128;

        if (tid < BMU) {
            s_sqA[tid] = g_sqn[p * NN + i0 + tid];
            s_fA[tid] = (float)((g_mask[i0 + tid] >> p) & 1);
        } else if (tid < BMU + BN) {
            int r = tid - BMU;
            s_sqB[r] = g_sqn[p * NN + j0 + r];
            s_fB[r] = (float)((g_mask[j0 + r] >> p) & 1);
        }

        float acc[8][4];
#pragma unroll
        for (int nt = 0; nt < 8; nt++)
#pragma unroll
            for (int e = 0; e < 4; e++) acc[nt][e] = 0.f;

        const __nv_bfloat16* gA0 = g_X + ((size_t)p * NN + i0) * DD;
        const __nv_bfloat16* gB0 = g_X + ((size_t)p * NN + j0) * DD;

        auto issue_load = [&](int s) {
            int slot = s & (NSTG - 1);
            int k0 = s << 5;
            uint32_t as = aB + slot * ATILEB, bs = bB + slot * BTILEB;
            { // A: 64 rows x 4 chunks = 256 -> 1 per thread
                int r = tid >> 2, kc = tid & 3;
                cp_async16(as + tile_off(r, kc), gA0 + (size_t)r * DD + k0 + (kc << 3));
            }
#pragma unroll
            for (int q = 0; q < 2; q++) { // B: 128 rows x 4 = 512 -> 2 per thread
                int lin = q * 256 + tid;
                int r = lin >> 2, kc = lin & 3;
                cp_async16(bs + tile_off(r, kc), gB0 + (size_t)r * DD + k0 + (kc << 3));
            }
        };

#pragma unroll
        for (int c = 0; c < NSTG - 1; c++) { issue_load(c); cp_commit(); }

        for (int s = 0; s < KST; s++) {
            if (s + NSTG - 1 < KST) issue_load(s + NSTG - 1);
            cp_commit();
            cp_wait<NSTG - 1>();
            __syncthreads();
            int slot = s & (NSTG - 1);
            uint32_t as = aB + slot * ATILEB, bs = bB + slot * BTILEB;
#pragma unroll
            for (int ks = 0; ks < 2; ks++) {
                int kc = ks * 2 + chalf;
                uint32_t a[4];
                ldsm_x4(a, as + tile_off(wm * 16 + rrow, kc));
                uint32_t bfr[4][4];
#pragma unroll
                for (int pr = 0; pr < 4; pr++)
                    ldsm_x4(bfr[pr], bs + tile_off(wn * 64 + pr * 16 + rrow, kc));
#pragma unroll
                for (int nt = 0; nt < 8; nt++)
                    mma_bf16(acc[nt], a, bfr[nt >> 1][nt & 1], bfr[nt >> 1][(nt & 1) + 2]);
            }
            __syncthreads();
        }

        // epilogue: masked pdist -> plane (plain stores: deterministic)
        float* plane = g_pd + ((size_t)(tile * PP + p) << 14) + (half * BMU) * 128;
        int r0 = wm * 16 + (lane >> 2), r1 = r0 + 8;
        float sa0 = s_sqA[r0], sa1 = s_sqA[r1];
        float fa0 = s_fA[r0], fa1 = s_fA[r1];
#pragma unroll
        for (int nt = 0; nt < 8; nt++) {
            int c0 = wn * 64 + nt * 8 + (lane & 3) * 2;
            float sb0 = s_sqB[c0], sb1 = s_sqB[c0 + 1];
            float fb0 = s_fB[c0], fb1 = s_fB[c0 + 1];
            float2 v0, v1;
            v0.x = fa0 * fb0 * fsqrt_approx(fmaxf(sa0 + sb0 - 2.f * acc[nt][0], 1e-12f));
            v0.y = fa0 * fb1 * fsqrt_approx(fmaxf(sa0 + sb1 - 2.f * acc[nt][1], 1e-12f));
            v1.x = fa1 * fb0 * fsqrt_approx(fmaxf(sa1 + sb0 - 2.f * acc[nt][2], 1e-12f));
            v1.y = fa1 * fb1 * fsqrt_approx(fmaxf(sa1 + sb1 - 2.f * acc[nt][3], 1e-12f));
            *(float2*)&plane[r0 * 128 + c0] = v0;
            *(float2*)&plane[r1 * 128 + c0] = v1;
        }
    }
}

// -------- reduce: per tile sum needed planes, hardest pos/neg row+col --------
__global__ void reduce_kernel() {
    __shared__ int s_mB[128], s_tB[128], s_cAp[128], s_cAn[128];
    int tile = blockIdx.x;
    int bi, bj; tile_decode(tile, bi, bj);
    int i0 = bi * 128, j0 = bj * 128;
    int tid = threadIdx.x;
    unsigned need = g_bmask[bi] & g_bmask[bj];

    if (tid < 128) {
        s_mB[tid] = g_mask[j0 + tid];
        s_tB[tid] = g_tgt[j0 + tid];
        s_cAp[tid] = 0; s_cAn[tid] = 0x7f800000;
    }
    __syncthreads();

    int r = tid >> 1, cbase = (tid & 1) * 64;
    int mAr = g_mask[i0 + r], tAr = g_tgt[i0 + r];
    const float* pl0 = g_pd + ((size_t)(tile * PP) << 14) + r * 128;
    const float INFF = __int_as_float(0x7f800000);
    float rp = 0.f, rn = INFF;
    for (int j = 0; j < 64; j++) {
        int c = cbase + j;
        float dsum = 0.f;
#pragma unroll
        for (int p = 0; p < PP; p++)
            if ((need >> p) & 1) dsum += __ldcg(&pl0[((size_t)p << 14) + c]);
        float d = __fdividef(dsum, (float)__popc(mAr & s_mB[c]));
        if (tAr == s_tB[c]) {
            rp = fmaxf(rp, d);
            atomicMax(&s_cAp[c], __float_as_int(d));
        } else {
            rn = fminf(rn, d);
            atomicMin(&s_cAn[c], __float_as_int(d));
        }
    }
    atomicMax(&g_ap[i0 + r], __float_as_int(rp));
    atomicMin(&g_an[i0 + r], __float_as_int(rn));
    __syncthreads();
    if (tid < 128) {
        atomicMax(&g_ap[j0 + tid], s_cAp[tid]); // column side (diag dupes harmless)
        atomicMin(&g_an[j0 + tid], s_cAn[tid]);
    }
}

// -------- final scalar reduction --------
__global__ void finish_kernel(float* __restrict__ out) {
    __shared__ float red[32][4];
    int tid = threadIdx.x;
    float ls = 0.f, ps = 0.f, aps = 0.f, ans = 0.f;
    for (int i = tid; i < NN; i += 1024) {
        float ap = __int_as_float(g_ap[i]);
        float an = __int_as_float(g_an[i]);
        ls += fmaxf(ap - an + 0.3f, 0.f);
        ps += (an > ap) ? 1.f : 0.f;
        aps += ap; ans += an;
    }
#pragma unroll
    for (int o = 16; o > 0; o >>= 1) {
        ls += __shfl_xor_sync(~0u, ls, o);
        ps += __shfl_xor_sync(~0u, ps, o);
        aps += __shfl_xor_sync(~0u, aps, o);
        ans += __shfl_xor_sync(~0u, ans, o);
    }
    int warp = tid >> 5, lane = tid & 31;
    if (lane == 0) { red[warp][0] = ls; red[warp][1] = ps; red[warp][2] = aps; red[warp][3] = ans; }
    __syncthreads();
    if (tid == 0) {
        float a = 0.f, bb = 0.f, cc = 0.f, dd = 0.f;
#pragma unroll
        for (int w = 0; w < 32; w++) { a += red[w][0]; bb += red[w][1]; cc += red[w][2]; dd += red[w][3]; }
        float inv = 1.0f / (float)NN;
        out[0] = a * inv;  // loss
        out[1] = bb * inv; // prec
        out[2] = cc * inv; // dist_ap mean
        out[3] = dd * inv; // dist_an mean
    }
}

extern "C" void kernel_launch(void* const* d_in, const int* in_sizes, int n_in,
                              void* d_out, int out_size) {
    const float* inputs = (const float*)d_in[0];
    const int* targets = (const int*)d_in[1];
    const int* part_labels = (const int*)d_in[2];
    float* out = (float*)d_out;
    (void)in_sizes; (void)n_in; (void)out_size;

    cudaFuncSetAttribute(unit_kernel, cudaFuncAttributeMaxDynamicSharedMemorySize, DYNB);

    setup_kernel<<<1, 1024>>>(part_labels, targets);
    pack_kernel<<<NN, 256>>>(inputs);
    unit_kernel<<<148, 256, DYNB>>>();
    reduce_kernel<<<NBLK, 256>>>();
    finish_kernel<<<1, 1024>>>(out);
}

// round 10
// speedup vs baseline: 1.3671x; 1.3671x over previous
#include <cuda_runtime.h>
#include <cuda_bf16.h>
#include <stdint.h>

#define NN 2048
#define DD 1024
#define PP 6
#define BM 128
#define BN 128
#define BK 32
#define NT 16                    // NN / 128
#define NBLK (NT * (NT + 1) / 2) // 136 triangular tiles
#define KST (DD / BK)            // 32 k-stages per part
#define NSTG 4                   // cp.async pipeline depth
#define TILEB (BM * BK * 2)      // 8192 bytes per A or B stage tile
#define DYNB (2 * NSTG * TILEB + 1024)
#define MAXU (NBLK * PP)         // 816 max units

// -------- scratch (static device globals: allocation-free) --------
__device__ __nv_bfloat16 g_X[(size_t)PP * NN * DD]; // packed+sorted [p][n][d] bf16
__device__ float g_sqn[PP * NN];                    // [p][n] squared norms (sorted)
__device__ int g_perm[NN];                          // original row -> sorted row
__device__ int g_mask[NN];                          // sorted-space visibility mask
__device__ int g_tgt[NN];                           // sorted-space targets
__device__ unsigned g_bmask[NT];                    // per 128-block OR mask
__device__ int g_units[MAXU];                       // unit list: tile | part<<8 (LPT order)
__device__ int g_nunits;
__device__ int g_ticket;
__device__ float g_pd[(size_t)NBLK * PP * 16384];   // per (tile,part) masked pdist planes
__device__ int g_ap[NN];                            // float bits, atomicMax (vals >= 0)
__device__ int g_an[NN];                            // float bits, atomicMin

// -------- PTX helpers --------
__device__ __forceinline__ void cp_async16(uint32_t dst, const void* src) {
    asm volatile("cp.async.cg.shared.global [%0], [%1], 16;\n" :: "r"(dst), "l"(src));
}
__device__ __forceinline__ void cp_commit() { asm volatile("cp.async.commit_group;\n"); }
template<int W> __device__ __forceinline__ void cp_wait() {
    asm volatile("cp.async.wait_group %0;\n" :: "n"(W));
}
__device__ __forceinline__ void ldsm_x4(uint32_t r[4], uint32_t addr) {
    asm volatile("ldmatrix.sync.aligned.m8n8.x4.shared.b16 {%0,%1,%2,%3}, [%4];\n"
                 : "=r"(r[0]), "=r"(r[1]), "=r"(r[2]), "=r"(r[3]) : "r"(addr));
}
__device__ __forceinline__ void mma_bf16(float c[4], const uint32_t a[4], uint32_t b0, uint32_t b1) {
    asm volatile("mma.sync.aligned.m16n8k16.row.col.f32.bf16.bf16.f32 "
                 "{%0,%1,%2,%3}, {%4,%5,%6,%7}, {%8,%9}, {%0,%1,%2,%3};\n"
                 : "+f"(c[0]), "+f"(c[1]), "+f"(c[2]), "+f"(c[3])
                 : "r"(a[0]), "r"(a[1]), "r"(a[2]), "r"(a[3]), "r"(b0), "r"(b1));
}
__device__ __forceinline__ float fsqrt_approx(float x) {
    float y; asm("sqrt.approx.f32 %0, %1;" : "=f"(y) : "f"(x)); return y;
}
// Swizzled byte offset inside a [rows x 32 bf16] stage tile (conflict-free).
__device__ __forceinline__ uint32_t tile_off(int r, int kc) {
    return (uint32_t)(((r >> 1) * 128) + ((((kc) + ((r & 1) << 2)) ^ ((r >> 1) & 7)) << 4));
}
__device__ __forceinline__ void tile_decode(int b, int& bi, int& bj) {
    bi = 0;
    while (b >= NT - bi) { b -= NT - bi; ++bi; }
    bj = bi + b;
}

// -------- setup: sort perm, masks, block masks, LPT-ordered unit list --------
__global__ void setup_kernel(const int* __restrict__ pl, const int* __restrict__ targets) {
    __shared__ uint8_t skey[NN];
    __shared__ uint16_t srank[NN];
    __shared__ int soff[9];
    __shared__ unsigned sbm[NT];
    __shared__ int ccnt[8], coff[8];
    int tid = threadIdx.x;
    for (int i = tid; i < NN; i += 1024)
        skey[i] = (uint8_t)(pl[2 * i] * 3 + (pl[2 * i + 1] - 3)); // key in 0..8
    __syncthreads();
    int w = tid >> 5, lane = tid & 31;
    if (w < 9) { // warp w ranks key w stably
        int base = 0;
        for (int c = 0; c < NN / 32; c++) {
            int i = c * 32 + lane;
            unsigned m = __ballot_sync(~0u, skey[i] == w);
            if (skey[i] == w) srank[i] = (uint16_t)(base + __popc(m & ((1u << lane) - 1u)));
            base += __popc(m);
        }
        if (lane == 0) soff[w] = base;
    }
    if (tid < 8) ccnt[tid] = 0;
    __syncthreads();
    if (tid == 0) {
        int acc = 0;
        for (int k = 0; k < 9; k++) { int c = soff[k]; soff[k] = acc; acc += c; }
    }
    __syncthreads();
    for (int i = tid; i < NN; i += 1024) {
        int pos = soff[skey[i]] + srank[i];
        g_perm[i] = pos;
        int st = pl[2 * i], en = pl[2 * i + 1];
        g_mask[pos] = (int)(((1u << (en + 1)) - 1u) & ~((1u << st) - 1u));
        g_tgt[pos] = targets[i];
    }
    __syncthreads();
    if (tid < NT) {
        unsigned u = 0;
        for (int r = 0; r < 128; r++) u |= (unsigned)g_mask[tid * 128 + r];
        sbm[tid] = u; g_bmask[tid] = u;
    }
    __syncthreads();
    int cls = 0, rank = 0;
    if (tid < NBLK) {
        int bi, bj; tile_decode(tid, bi, bj);
        cls = __popc(sbm[bi] & sbm[bj]); // in 2..6
        rank = atomicAdd(&ccnt[cls], 1);
    }
    __syncthreads();
    if (tid == 0) {
        int acc = 0;
        for (int c = 6; c >= 1; c--) { coff[c] = acc; acc += ccnt[c] * c; } // LPT: big popc first
        g_nunits = acc;
        g_ticket = 0;
    }
    __syncthreads();
    if (tid < NBLK) {
        int bi, bj; tile_decode(tid, bi, bj);
        unsigned need = sbm[bi] & sbm[bj];
        int o = coff[cls] + rank * cls;
        for (int p = 0; p < PP; p++) if ((need >> p) & 1)
            g_units[o++] = tid | (p << 8);
    }
}

// -------- pack: fp32 [n][d][P] -> bf16 [p][perm(n)][d]; sqn; init ap/an --------
__global__ void pack_kernel(const float* __restrict__ in) {
    int i = blockIdx.x;
    int tid = threadIdx.x;
    int P = g_perm[i];
    float acc[PP];
#pragma unroll
    for (int p = 0; p < PP; p++) acc[p] = 0.f;
    const float* row = in + (size_t)i * DD * PP;
    for (int dd = tid; dd < DD; dd += 256) {
#pragma unroll
        for (int p = 0; p < PP; p++) {
            float v = row[dd * PP + p];
            __nv_bfloat16 b = __float2bfloat16(v);
            float vb = __bfloat162float(b);
            g_X[((size_t)p * NN + P) * DD + dd] = b;
            acc[p] = fmaf(vb, vb, acc[p]);
        }
    }
    __shared__ float s[8][PP];
    int warp = tid >> 5, lane = tid & 31;
#pragma unroll
    for (int p = 0; p < PP; p++) {
        float v = acc[p];
#pragma unroll
        for (int o = 16; o > 0; o >>= 1) v += __shfl_xor_sync(~0u, v, o);
        if (lane == 0) s[warp][p] = v;
    }
    __syncthreads();
    if (tid < PP) {
        float v = 0.f;
#pragma unroll
        for (int w = 0; w < 8; w++) v += s[w][tid];
        g_sqn[tid * NN + P] = v;
    }
    if (tid == 0) { g_ap[i] = 0; g_an[i] = 0x7f800000; }
}

// -------- unit kernel: persistent CTAs, ticket over (tile,part), M=128 --------
extern __shared__ __align__(16) char dynsmem[];

__global__ void __launch_bounds__(256, 1) unit_kernel() {
    __shared__ float s_sqA[BM], s_sqB[BN], s_fA[BM], s_fB[BN];
    __shared__ int s_unit;

    int tid = threadIdx.x;
    int lane = tid & 31, warp = tid >> 5;
    int wm = warp >> 1, wn = warp & 1; // 4x2 warp grid, warp tile 32x64

    uint32_t dynbase = (uint32_t)__cvta_generic_to_shared(dynsmem);
    dynbase = (dynbase + 1023u) & ~1023u;
    uint32_t aB = dynbase, bB = dynbase + NSTG * TILEB;

    int rrow = ((lane >> 3) & 1) * 8 + (lane & 7);
    int chalf = lane >> 4;

    while (true) {
        __syncthreads(); // protect smem + stage buffers reuse across units
        if (tid == 0) {
            int t = atomicAdd(&g_ticket, 1);
            s_unit = (t < g_nunits) ? g_units[t] : -1;
        }
        __syncthreads();
        int u = s_unit;
        if (u < 0) break;
        int tile = u & 255, p = (u >> 8) & 15;
        int bi, bj; tile_decode(tile, bi, bj);
        int i0 = bi * 128, j0 = bj * 128;

        if (tid < BM) {
            s_sqA[tid] = g_sqn[p * NN + i0 + tid];
            s_fA[tid] = (float)((g_mask[i0 + tid] >> p) & 1);
        } else {
            int r = tid - BM;
            s_sqB[r] = g_sqn[p * NN + j0 + r];
            s_fB[r] = (float)((g_mask[j0 + r] >> p) & 1);
        }

        float acc[2][8][4];
#pragma unroll
        for (int mt = 0; mt < 2; mt++)
#pragma unroll
            for (int nt = 0; nt < 8; nt++)
#pragma unroll
                for (int e = 0; e < 4; e++) acc[mt][nt][e] = 0.f;

        const __nv_bfloat16* gA0 = g_X + ((size_t)p * NN + i0) * DD;
        const __nv_bfloat16* gB0 = g_X + ((size_t)p * NN + j0) * DD;

        auto issue_load = [&](int s) {
            int slot = s & (NSTG - 1);
            int k0 = s << 5;
            uint32_t as = aB + slot * TILEB, bs = bB + slot * TILEB;
#pragma unroll
            for (int q = 0; q < 2; q++) {
                int lin = q * 256 + tid;
                int r = lin >> 2, kc = lin & 3;
                uint32_t off = tile_off(r, kc);
                cp_async16(as + off, gA0 + (size_t)r * DD + k0 + (kc << 3));
                cp_async16(bs + off, gB0 + (size_t)r * DD + k0 + (kc << 3));
            }
        };

#pragma unroll
        for (int c = 0; c < NSTG - 1; c++) { issue_load(c); cp_commit(); }

        for (int s = 0; s < KST; s++) {
            if (s + NSTG - 1 < KST) issue_load(s + NSTG - 1);
            cp_commit();
            cp_wait<NSTG - 1>();
            __syncthreads();
            int slot = s & (NSTG - 1);
            uint32_t as = aB + slot * TILEB, bs = bB + slot * TILEB;
#pragma unroll
            for (int ks = 0; ks < 2; ks++) {
                int kc = ks * 2 + chalf;
                uint32_t a[2][4];
#pragma unroll
                for (int mt = 0; mt < 2; mt++)
                    ldsm_x4(a[mt], as + tile_off(wm * 32 + mt * 16 + rrow, kc));
                uint32_t bfr[4][4];
#pragma unroll
                for (int pr = 0; pr < 4; pr++)
                    ldsm_x4(bfr[pr], bs + tile_off(wn * 64 + pr * 16 + rrow, kc));
#pragma unroll
                for (int mt = 0; mt < 2; mt++)
#pragma unroll
                    for (int nt = 0; nt < 8; nt++)
                        mma_bf16(acc[mt][nt], a[mt], bfr[nt >> 1][nt & 1], bfr[nt >> 1][(nt & 1) + 2]);
            }
            __syncthreads();
        }

        // epilogue: masked pdist -> plane (plain stores: deterministic)
        float* plane = g_pd + ((size_t)(tile * PP + p) << 14);
#pragma unroll
        for (int mt = 0; mt < 2; mt++) {
            int r0 = wm * 32 + mt * 16 + (lane >> 2), r1 = r0 + 8;
            float sa0 = s_sqA[r0], sa1 = s_sqA[r1];
            float fa0 = s_fA[r0], fa1 = s_fA[r1];
#pragma unroll
            for (int nt = 0; nt < 8; nt++) {
                int c0 = wn * 64 + nt * 8 + (lane & 3) * 2;
                float sb0 = s_sqB[c0], sb1 = s_sqB[c0 + 1];
                float fb0 = s_fB[c0], fb1 = s_fB[c0 + 1];
                float2 v0, v1;
                v0.x = fa0 * fb0 * fsqrt_approx(fmaxf(sa0 + sb0 - 2.f * acc[mt][nt][0], 1e-12f));
                v0.y = fa0 * fb1 * fsqrt_approx(fmaxf(sa0 + sb1 - 2.f * acc[mt][nt][1], 1e-12f));
                v1.x = fa1 * fb0 * fsqrt_approx(fmaxf(sa1 + sb0 - 2.f * acc[mt][nt][2], 1e-12f));
                v1.y = fa1 * fb1 * fsqrt_approx(fmaxf(sa1 + sb1 - 2.f * acc[mt][nt][3], 1e-12f));
                *(float2*)&plane[r0 * 128 + c0] = v0;
                *(float2*)&plane[r1 * 128 + c0] = v1;
            }
        }
    }
}

// -------- reduce: coalesced float4 plane sums; shuffle/register reductions --------
__global__ void reduce_kernel() {
    __shared__ int s_mB[128], s_tB[128];
    __shared__ float s_cp[8][128], s_cn[8][128];
    int tile = blockIdx.x;
    int bi, bj; tile_decode(tile, bi, bj);
    int i0 = bi * 128, j0 = bj * 128;
    int tid = threadIdx.x, w = tid >> 5, l = tid & 31;
    unsigned need = g_bmask[bi] & g_bmask[bj];

    if (tid < 128) { s_mB[tid] = g_mask[j0 + tid]; s_tB[tid] = g_tgt[j0 + tid]; }
    __syncthreads();

    const float INFF = __int_as_float(0x7f800000);
    int c0 = 4 * l;
    int mB4[4], tB4[4];
#pragma unroll
    for (int q = 0; q < 4; q++) { mB4[q] = s_mB[c0 + q]; tB4[q] = s_tB[c0 + q]; }
    float cAp[4] = {0.f, 0.f, 0.f, 0.f};
    float cAn[4] = {INFF, INFF, INFF, INFF};

    const float* base = g_pd + ((size_t)(tile * PP) << 14);
    for (int k = 0; k < 16; k++) {
        int r = k * 8 + w;
        float4 dsum = make_float4(0.f, 0.f, 0.f, 0.f);
#pragma unroll
        for (int p = 0; p < PP; p++) if ((need >> p) & 1) {
            float4 v = *(const float4*)&base[((size_t)p << 14) + r * 128 + c0];
            dsum.x += v.x; dsum.y += v.y; dsum.z += v.z; dsum.w += v.w;
        }
        int mA = g_mask[i0 + r], tA = g_tgt[i0 + r];
        float d[4];
        d[0] = __fdividef(dsum.x, (float)__popc(mA & mB4[0]));
        d[1] = __fdividef(dsum.y, (float)__popc(mA & mB4[1]));
        d[2] = __fdividef(dsum.z, (float)__popc(mA & mB4[2]));
        d[3] = __fdividef(dsum.w, (float)__popc(mA & mB4[3]));
        float rp = 0.f, rn = INFF;
#pragma unroll
        for (int q = 0; q < 4; q++) {
            if (tA == tB4[q]) { rp = fmaxf(rp, d[q]); cAp[q] = fmaxf(cAp[q], d[q]); }
            else             { rn = fminf(rn, d[q]); cAn[q] = fminf(cAn[q], d[q]); }
        }
#pragma unroll
        for (int o = 16; o > 0; o >>= 1) {
            rp = fmaxf(rp, __shfl_xor_sync(~0u, rp, o));
            rn = fminf(rn, __shfl_xor_sync(~0u, rn, o));
        }
        if (l == 0) {
            atomicMax(&g_ap[i0 + r], __float_as_int(rp));
            atomicMin(&g_an[i0 + r], __float_as_int(rn));
        }
    }
#pragma unroll
    for (int q = 0; q < 4; q++) { s_cp[w][c0 + q] = cAp[q]; s_cn[w][c0 + q] = cAn[q]; }
    __syncthreads();
    if (tid < 128) {
        float ap = 0.f, an = INFF;
#pragma unroll
        for (int ww = 0; ww < 8; ww++) {
            ap = fmaxf(ap, s_cp[ww][tid]);
            an = fminf(an, s_cn[ww][tid]);
        }
        atomicMax(&g_ap[j0 + tid], __float_as_int(ap)); // column side (diag dupes harmless)
        atomicMin(&g_an[j0 + tid], __float_as_int(an));
    }
}

// -------- final scalar reduction --------
__global__ void finish_kernel(float* __restrict__ out) {
    __shared__ float red[32][4];
    int tid = threadIdx.x;
    float ls = 0.f, ps = 0.f, aps = 0.f, ans = 0.f;
    for (int i = tid; i < NN; i += 1024) {
        float ap = __int_as_float(g_ap[i]);
        float an = __int_as_float(g_an[i]);
        ls += fmaxf(ap - an + 0.3f, 0.f);
        ps += (an > ap) ? 1.f : 0.f;
        aps += ap; ans += an;
    }
#pragma unroll
    for (int o = 16; o > 0; o >>= 1) {
        ls += __shfl_xor_sync(~0u, ls, o);
        ps += __shfl_xor_sync(~0u, ps, o);
        aps += __shfl_xor_sync(~0u, aps, o);
        ans += __shfl_xor_sync(~0u, ans, o);
    }
    int warp = tid >> 5, lane = tid & 31;
    if (lane == 0) { red[warp][0] = ls; red[warp][1] = ps; red[warp][2] = aps; red[warp][3] = ans; }
    __syncthreads();
    if (tid == 0) {
        float a = 0.f, bb = 0.f, cc = 0.f, dd = 0.f;
#pragma unroll
        for (int w = 0; w < 32; w++) { a += red[w][0]; bb += red[w][1]; cc += red[w][2]; dd += red[w][3]; }
        float inv = 1.0f / (float)NN;
        out[0] = a * inv;  // loss
        out[1] = bb * inv; // prec
        out[2] = cc * inv; // dist_ap mean
        out[3] = dd * inv; // dist_an mean
    }
}

extern "C" void kernel_launch(void* const* d_in, const int* in_sizes, int n_in,
                              void* d_out, int out_size) {
    const float* inputs = (const float*)d_in[0];
    const int* targets = (const int*)d_in[1];
    const int* part_labels = (const int*)d_in[2];
    float* out = (float*)d_out;
    (void)in_sizes; (void)n_in; (void)out_size;

    cudaFuncSetAttribute(unit_kernel, cudaFuncAttributeMaxDynamicSharedMemorySize, DYNB);

    setup_kernel<<<1, 1024>>>(part_labels, targets);
    pack_kernel<<<NN, 256>>>(inputs);
    unit_kernel<<<148, 256, DYNB>>>();
    reduce_kernel<<<NBLK, 256>>>();
    finish_kernel<<<1, 1024>>>(out);
}

// round 11
// speedup vs baseline: 1.4744x; 1.0785x over previous
#include <cuda_runtime.h>
#include <cuda_bf16.h>
#include <stdint.h>

#define NN 2048
#define DD 1024
#define PP 6
#define BM 128
#define BN 128
#define BK 32
#define NT 16                    // NN / 128
#define NBLK (NT * (NT + 1) / 2) // 136 triangular tiles
#define KST (DD / BK)            // 32 k-stages per part
#define NSTG 4                   // cp.async pipeline depth
#define TILEB (BM * BK * 2)      // 8192 bytes per A or B stage tile
#define DYNB (2 * NSTG * TILEB + 1024)
#define MAXU (NBLK * PP)         // 816 max units

// -------- scratch (static device globals: allocation-free) --------
__device__ __nv_bfloat16 g_X[(size_t)PP * NN * DD]; // packed+sorted [p][n][d] bf16
__device__ float g_sqn[PP * NN];                    // [p][n] squared norms (sorted)
__device__ int g_perm[NN];                          // original row -> sorted row
__device__ int g_mask[NN];                          // sorted-space visibility mask
__device__ int g_tgt[NN];                           // sorted-space targets
__device__ unsigned g_bmask[NT];                    // per 128-block OR mask
__device__ int g_units[MAXU];                       // unit list: tile | part<<8 (LPT order)
__device__ int g_nunits;
__device__ int g_ticket;
__device__ float g_pd[(size_t)NBLK * PP * 16384];   // per (tile,part) masked pdist planes
__device__ int g_ap[NN];                            // float bits, atomicMax (vals >= 0)
__device__ int g_an[NN];                            // float bits, atomicMin

// -------- PTX helpers --------
__device__ __forceinline__ void cp_async16(uint32_t dst, const void* src) {
    asm volatile("cp.async.cg.shared.global [%0], [%1], 16;\n" :: "r"(dst), "l"(src));
}
__device__ __forceinline__ void cp_commit() { asm volatile("cp.async.commit_group;\n"); }
template<int W> __device__ __forceinline__ void cp_wait() {
    asm volatile("cp.async.wait_group %0;\n" :: "n"(W));
}
__device__ __forceinline__ void ldsm_x4(uint32_t r[4], uint32_t addr) {
    asm volatile("ldmatrix.sync.aligned.m8n8.x4.shared.b16 {%0,%1,%2,%3}, [%4];\n"
                 : "=r"(r[0]), "=r"(r[1]), "=r"(r[2]), "=r"(r[3]) : "r"(addr));
}
__device__ __forceinline__ void mma_bf16(float c[4], const uint32_t a[4], uint32_t b0, uint32_t b1) {
    asm volatile("mma.sync.aligned.m16n8k16.row.col.f32.bf16.bf16.f32 "
                 "{%0,%1,%2,%3}, {%4,%5,%6,%7}, {%8,%9}, {%0,%1,%2,%3};\n"
                 : "+f"(c[0]), "+f"(c[1]), "+f"(c[2]), "+f"(c[3])
                 : "r"(a[0]), "r"(a[1]), "r"(a[2]), "r"(a[3]), "r"(b0), "r"(b1));
}
__device__ __forceinline__ float fsqrt_approx(float x) {
    float y; asm("sqrt.approx.f32 %0, %1;" : "=f"(y) : "f"(x)); return y;
}
// Swizzled byte offset inside a [rows x 32 bf16] stage tile (conflict-free).
__device__ __forceinline__ uint32_t tile_off(int r, int kc) {
    return (uint32_t)(((r >> 1) * 128) + ((((kc) + ((r & 1) << 2)) ^ ((r >> 1) & 7)) << 4));
}
__device__ __forceinline__ void tile_decode(int b, int& bi, int& bj) {
    bi = 0;
    while (b >= NT - bi) { b -= NT - bi; ++bi; }
    bj = bi + b;
}

// -------- setup: sort perm, masks, block masks, LPT-ordered unit list --------
__global__ void setup_kernel(const int* __restrict__ pl, const int* __restrict__ targets) {
    __shared__ uint8_t skey[NN];
    __shared__ uint16_t srank[NN];
    __shared__ int soff[9];
    __shared__ unsigned sbm[NT];
    __shared__ int ccnt[8], coff[8];
    int tid = threadIdx.x;
    for (int i = tid; i < NN; i += 1024)
        skey[i] = (uint8_t)(pl[2 * i] * 3 + (pl[2 * i + 1] - 3)); // key in 0..8
    __syncthreads();
    int w = tid >> 5, lane = tid & 31;
    if (w < 9) { // warp w ranks key w stably
        int base = 0;
        for (int c = 0; c < NN / 32; c++) {
            int i = c * 32 + lane;
            unsigned m = __ballot_sync(~0u, skey[i] == w);
            if (skey[i] == w) srank[i] = (uint16_t)(base + __popc(m & ((1u << lane) - 1u)));
            base += __popc(m);
        }
        if (lane == 0) soff[w] = base;
    }
    if (tid < 8) ccnt[tid] = 0;
    __syncthreads();
    if (tid == 0) {
        int acc = 0;
        for (int k = 0; k < 9; k++) { int c = soff[k]; soff[k] = acc; acc += c; }
    }
    __syncthreads();
    for (int i = tid; i < NN; i += 1024) {
        int pos = soff[skey[i]] + srank[i];
        g_perm[i] = pos;
        int st = pl[2 * i], en = pl[2 * i + 1];
        g_mask[pos] = (int)(((1u << (en + 1)) - 1u) & ~((1u << st) - 1u));
        g_tgt[pos] = targets[i];
    }
    __syncthreads();
    if (tid < NT) {
        unsigned u = 0;
        for (int r = 0; r < 128; r++) u |= (unsigned)g_mask[tid * 128 + r];
        sbm[tid] = u; g_bmask[tid] = u;
    }
    __syncthreads();
    int cls = 0, rank = 0;
    if (tid < NBLK) {
        int bi, bj; tile_decode(tid, bi, bj);
        cls = __popc(sbm[bi] & sbm[bj]); // in 2..6
        rank = atomicAdd(&ccnt[cls], 1);
    }
    __syncthreads();
    if (tid == 0) {
        int acc = 0;
        for (int c = 6; c >= 1; c--) { coff[c] = acc; acc += ccnt[c] * c; } // LPT: big popc first
        g_nunits = acc;
        g_ticket = 0;
    }
    __syncthreads();
    if (tid < NBLK) {
        int bi, bj; tile_decode(tid, bi, bj);
        unsigned need = sbm[bi] & sbm[bj];
        int o = coff[cls] + rank * cls;
        for (int p = 0; p < PP; p++) if ((need >> p) & 1)
            g_units[o++] = tid | (p << 8);
    }
}

// -------- pack: fp32 [n][d][P] -> bf16 [p][perm(n)][d]; sqn; init ap/an --------
__global__ void pack_kernel(const float* __restrict__ in) {
    int i = blockIdx.x;
    int tid = threadIdx.x;
    int P = g_perm[i];
    float acc[PP];
#pragma unroll
    for (int p = 0; p < PP; p++) acc[p] = 0.f;
    const float* row = in + (size_t)i * DD * PP;
    for (int dd = tid; dd < DD; dd += 256) {
#pragma unroll
        for (int p = 0; p < PP; p++) {
            float v = row[dd * PP + p];
            __nv_bfloat16 b = __float2bfloat16(v);
            float vb = __bfloat162float(b);
            g_X[((size_t)p * NN + P) * DD + dd] = b;
            acc[p] = fmaf(vb, vb, acc[p]);
        }
    }
    __shared__ float s[8][PP];
    int warp = tid >> 5, lane = tid & 31;
#pragma unroll
    for (int p = 0; p < PP; p++) {
        float v = acc[p];
#pragma unroll
        for (int o = 16; o > 0; o >>= 1) v += __shfl_xor_sync(~0u, v, o);
        if (lane == 0) s[warp][p] = v;
    }
    __syncthreads();
    if (tid < PP) {
        float v = 0.f;
#pragma unroll
        for (int w = 0; w < 8; w++) v += s[w][tid];
        g_sqn[tid * NN + P] = v;
    }
    if (tid == 0) { g_ap[i] = 0; g_an[i] = 0x7f800000; }
}

// -------- unit kernel: persistent CTAs, ticket over (tile,part), M=128 --------
extern __shared__ __align__(16) char dynsmem[];

__global__ void __launch_bounds__(256, 1) unit_kernel() {
    __shared__ float s_sqA[BM], s_sqB[BN], s_fA[BM], s_fB[BN];
    __shared__ int s_unit;

    int tid = threadIdx.x;
    int lane = tid & 31, warp = tid >> 5;
    int wm = warp >> 1, wn = warp & 1; // 4x2 warp grid, warp tile 32x64

    uint32_t dynbase = (uint32_t)__cvta_generic_to_shared(dynsmem);
    dynbase = (dynbase + 1023u) & ~1023u;
    uint32_t aB = dynbase, bB = dynbase + NSTG * TILEB;

    int rrow = ((lane >> 3) & 1) * 8 + (lane & 7);
    int chalf = lane >> 4;

    while (true) {
        __syncthreads(); // protect smem + stage buffers reuse across units
        if (tid == 0) {
            int t = atomicAdd(&g_ticket, 1);
            s_unit = (t < g_nunits) ? g_units[t] : -1;
        }
        __syncthreads();
        int u = s_unit;
        if (u < 0) break;
        int tile = u & 255, p = (u >> 8) & 15;
        int bi, bj; tile_decode(tile, bi, bj);
        int i0 = bi * 128, j0 = bj * 128;

        if (tid < BM) {
            s_sqA[tid] = g_sqn[p * NN + i0 + tid];
            s_fA[tid] = (float)((g_mask[i0 + tid] >> p) & 1);
        } else {
            int r = tid - BM;
            s_sqB[r] = g_sqn[p * NN + j0 + r];
            s_fB[r] = (float)((g_mask[j0 + r] >> p) & 1);
        }

        float acc[2][8][4];
#pragma unroll
        for (int mt = 0; mt < 2; mt++)
#pragma unroll
            for (int nt = 0; nt < 8; nt++)
#pragma unroll
                for (int e = 0; e < 4; e++) acc[mt][nt][e] = 0.f;

        const __nv_bfloat16* gA0 = g_X + ((size_t)p * NN + i0) * DD;
        const __nv_bfloat16* gB0 = g_X + ((size_t)p * NN + j0) * DD;

        auto issue_load = [&](int s) {
            int slot = s & (NSTG - 1);
            int k0 = s << 5;
            uint32_t as = aB + slot * TILEB, bs = bB + slot * TILEB;
#pragma unroll
            for (int q = 0; q < 2; q++) {
                int lin = q * 256 + tid;
                int r = lin >> 2, kc = lin & 3;
                uint32_t off = tile_off(r, kc);
                cp_async16(as + off, gA0 + (size_t)r * DD + k0 + (kc << 3));
                cp_async16(bs + off, gB0 + (size_t)r * DD + k0 + (kc << 3));
            }
        };

#pragma unroll
        for (int c = 0; c < NSTG - 1; c++) { issue_load(c); cp_commit(); }

        for (int s = 0; s < KST; s++) {
            if (s + NSTG - 1 < KST) issue_load(s + NSTG - 1);
            cp_commit();
            cp_wait<NSTG - 1>();
            __syncthreads();
            int slot = s & (NSTG - 1);
            uint32_t as = aB + slot * TILEB, bs = bB + slot * TILEB;
#pragma unroll
            for (int ks = 0; ks < 2; ks++) {
                int kc = ks * 2 + chalf;
                uint32_t a[2][4];
#pragma unroll
                for (int mt = 0; mt < 2; mt++)
                    ldsm_x4(a[mt], as + tile_off(wm * 32 + mt * 16 + rrow, kc));
                uint32_t bfr[4][4];
#pragma unroll
                for (int pr = 0; pr < 4; pr++)
                    ldsm_x4(bfr[pr], bs + tile_off(wn * 64 + pr * 16 + rrow, kc));
#pragma unroll
                for (int mt = 0; mt < 2; mt++)
#pragma unroll
                    for (int nt = 0; nt < 8; nt++)
                        mma_bf16(acc[mt][nt], a[mt], bfr[nt >> 1][nt & 1], bfr[nt >> 1][(nt & 1) + 2]);
            }
            __syncthreads();
        }

        // epilogue: masked pdist -> plane (plain stores: deterministic)
        float* plane = g_pd + ((size_t)(tile * PP + p) << 14);
#pragma unroll
        for (int mt = 0; mt < 2; mt++) {
            int r0 = wm * 32 + mt * 16 + (lane >> 2), r1 = r0 + 8;
            float sa0 = s_sqA[r0], sa1 = s_sqA[r1];
            float fa0 = s_fA[r0], fa1 = s_fA[r1];
#pragma unroll
            for (int nt = 0; nt < 8; nt++) {
                int c0 = wn * 64 + nt * 8 + (lane & 3) * 2;
                float sb0 = s_sqB[c0], sb1 = s_sqB[c0 + 1];
                float fb0 = s_fB[c0], fb1 = s_fB[c0 + 1];
                float2 v0, v1;
                v0.x = fa0 * fb0 * fsqrt_approx(fmaxf(sa0 + sb0 - 2.f * acc[mt][nt][0], 1e-12f));
                v0.y = fa0 * fb1 * fsqrt_approx(fmaxf(sa0 + sb1 - 2.f * acc[mt][nt][1], 1e-12f));
                v1.x = fa1 * fb0 * fsqrt_approx(fmaxf(sa1 + sb0 - 2.f * acc[mt][nt][2], 1e-12f));
                v1.y = fa1 * fb1 * fsqrt_approx(fmaxf(sa1 + sb1 - 2.f * acc[mt][nt][3], 1e-12f));
                *(float2*)&plane[r0 * 128 + c0] = v0;
                *(float2*)&plane[r1 * 128 + c0] = v1;
            }
        }
    }
}

// -------- reduce: 4 row-chunks per tile (544 CTAs) for DRAM-level MLP --------
__global__ void reduce_kernel() {
    __shared__ int s_mB[128], s_tB[128];
    __shared__ float s_cp[8][128], s_cn[8][128];
    int tile = blockIdx.x >> 2, chunk = blockIdx.x & 3;
    int bi, bj; tile_decode(tile, bi, bj);
    int i0 = bi * 128, j0 = bj * 128;
    int tid = threadIdx.x, w = tid >> 5, l = tid & 31;
    unsigned need = g_bmask[bi] & g_bmask[bj];

    if (tid < 128) { s_mB[tid] = g_mask[j0 + tid]; s_tB[tid] = g_tgt[j0 + tid]; }
    __syncthreads();

    const float INFF = __int_as_float(0x7f800000);
    int c0 = 4 * l;
    int mB4[4], tB4[4];
#pragma unroll
    for (int q = 0; q < 4; q++) { mB4[q] = s_mB[c0 + q]; tB4[q] = s_tB[c0 + q]; }
    float cAp[4] = {0.f, 0.f, 0.f, 0.f};
    float cAn[4] = {INFF, INFF, INFF, INFF};

    const float* base = g_pd + ((size_t)(tile * PP) << 14);
#pragma unroll
    for (int k = 0; k < 4; k++) {
        int r = chunk * 32 + k * 8 + w;
        float4 dsum = make_float4(0.f, 0.f, 0.f, 0.f);
#pragma unroll
        for (int p = 0; p < PP; p++) if ((need >> p) & 1) {
            float4 v = *(const float4*)&base[((size_t)p << 14) + r * 128 + c0];
            dsum.x += v.x; dsum.y += v.y; dsum.z += v.z; dsum.w += v.w;
        }
        int mA = g_mask[i0 + r], tA = g_tgt[i0 + r];
        float d[4];
        d[0] = __fdividef(dsum.x, (float)__popc(mA & mB4[0]));
        d[1] = __fdividef(dsum.y, (float)__popc(mA & mB4[1]));
        d[2] = __fdividef(dsum.z, (float)__popc(mA & mB4[2]));
        d[3] = __fdividef(dsum.w, (float)__popc(mA & mB4[3]));
        float rp = 0.f, rn = INFF;
#pragma unroll
        for (int q = 0; q < 4; q++) {
            if (tA == tB4[q]) { rp = fmaxf(rp, d[q]); cAp[q] = fmaxf(cAp[q], d[q]); }
            else             { rn = fminf(rn, d[q]); cAn[q] = fminf(cAn[q], d[q]); }
        }
#pragma unroll
        for (int o = 16; o > 0; o >>= 1) {
            rp = fmaxf(rp, __shfl_xor_sync(~0u, rp, o));
            rn = fminf(rn, __shfl_xor_sync(~0u, rn, o));
        }
        if (l == 0) {
            atomicMax(&g_ap[i0 + r], __float_as_int(rp));
            atomicMin(&g_an[i0 + r], __float_as_int(rn));
        }
    }
#pragma unroll
    for (int q = 0; q < 4; q++) { s_cp[w][c0 + q] = cAp[q]; s_cn[w][c0 + q] = cAn[q]; }
    __syncthreads();
    if (tid < 128) {
        float ap = 0.f, an = INFF;
#pragma unroll
        for (int ww = 0; ww < 8; ww++) {
            ap = fmaxf(ap, s_cp[ww][tid]);
            an = fminf(an, s_cn[ww][tid]);
        }
        atomicMax(&g_ap[j0 + tid], __float_as_int(ap)); // column side (diag dupes harmless)
        atomicMin(&g_an[j0 + tid], __float_as_int(an));
    }
}

// -------- final scalar reduction --------
__global__ void finish_kernel(float* __restrict__ out) {
    __shared__ float red[32][4];
    int tid = threadIdx.x;
    float ls = 0.f, ps = 0.f, aps = 0.f, ans = 0.f;
    for (int i = tid; i < NN; i += 1024) {
        float ap = __int_as_float(g_ap[i]);
        float an = __int_as_float(g_an[i]);
        ls += fmaxf(ap - an + 0.3f, 0.f);
        ps += (an > ap) ? 1.f : 0.f;
        aps += ap; ans += an;
    }
#pragma unroll
    for (int o = 16; o > 0; o >>= 1) {
        ls += __shfl_xor_sync(~0u, ls, o);
        ps += __shfl_xor_sync(~0u, ps, o);
        aps += __shfl_xor_sync(~0u, aps, o);
        ans += __shfl_xor_sync(~0u, ans, o);
    }
    int warp = tid >> 5, lane = tid & 31;
    if (lane == 0) { red[warp][0] = ls; red[warp][1] = ps; red[warp][2] = aps; red[warp][3] = ans; }
    __syncthreads();
    if (tid == 0) {
        float a = 0.f, bb = 0.f, cc = 0.f, dd = 0.f;
#pragma unroll
        for (int w = 0; w < 32; w++) { a += red[w][0]; bb += red[w][1]; cc += red[w][2]; dd += red[w][3]; }
        float inv = 1.0f / (float)NN;
        out[0] = a * inv;  // loss
        out[1] = bb * inv; // prec
        out[2] = cc * inv; // dist_ap mean
        out[3] = dd * inv; // dist_an mean
    }
}

extern "C" void kernel_launch(void* const* d_in, const int* in_sizes, int n_in,
                              void* d_out, int out_size) {
    const float* inputs = (const float*)d_in[0];
    const int* targets = (const int*)d_in[1];
    const int* part_labels = (const int*)d_in[2];
    float* out = (float*)d_out;
    (void)in_sizes; (void)n_in; (void)out_size;

    cudaFuncSetAttribute(unit_kernel, cudaFuncAttributeMaxDynamicSharedMemorySize, DYNB);

    setup_kernel<<<1, 1024>>>(part_labels, targets);
    pack_kernel<<<NN, 256>>>(inputs);
    unit_kernel<<<148, 256, DYNB>>>();
    reduce_kernel<<<NBLK * 4, 256>>>();
    finish_kernel<<<1, 1024>>>(out);
}